// round 1
// baseline (speedup 1.0000x reference)
#include <cuda_runtime.h>
#include <cstdint>

#define BB   16
#define NN   8192
#define KNB  16
#define MTOT (BB*NN)      // 131072
#define H3   64
#define H2   128
#define H1   512
#define EPSBN 1e-5f

typedef unsigned long long ull;
typedef unsigned int uint;

// ---------------- scratch (static device globals; no allocs allowed) ----------------
__device__ float g_pre1[MTOT*H3];
__device__ float g_agg1[MTOT*H3];
__device__ float g_pre2[MTOT*H2];
__device__ float g_agg2[MTOT*H2];
__device__ float g_z2[MTOT*3];
__device__ float g_sum1[H3], g_sq1[H3];
__device__ float g_sum2[H2], g_sq2[H2];
__device__ float g_sum3[H1], g_sq3[H1];
__device__ uint  g_maxk[BB*H1], g_mink[BB*H1];
__device__ float g_bn1[2*H3];
__device__ float g_bn2[2*H2];
__device__ float g_pool[BB*H1];
__device__ float g_pre4[BB*H1];
__device__ float g_dc1[BB*3], g_dc2[BB*3];
__device__ float g_d1p[6];
__device__ float g_sumd[3], g_sqd[3];

// ---------------- helpers ----------------
__device__ __forceinline__ uint fkey(float f){
    uint u = __float_as_uint(f);
    return (u & 0x80000000u) ? ~u : (u | 0x80000000u);
}
__device__ __forceinline__ float keyf(uint k){
    uint u = (k & 0x80000000u) ? (k ^ 0x80000000u) : ~k;
    return __uint_as_float(u);
}
__device__ __forceinline__ ull pack2(float x, float y){
    ull r; asm("mov.b64 %0, {%1,%2};" : "=l"(r) : "f"(x), "f"(y)); return r;
}
__device__ __forceinline__ float2 unpack2(ull v){
    float2 f; asm("mov.b64 {%0,%1}, %2;" : "=f"(f.x), "=f"(f.y) : "l"(v)); return f;
}
__device__ __forceinline__ void ffma2(ull &d, ull a, ull b){
    asm("fma.rn.f32x2 %0, %1, %2, %0;" : "+l"(d) : "l"(a), "l"(b));
}

// ---------------- kernels ----------------
__global__ void k_zero(){
    int i = blockIdx.x*blockDim.x + threadIdx.x;
    if (i < BB*H1){ g_maxk[i]=0u; g_mink[i]=0xFFFFFFFFu; }
    if (i < H1){ g_sum3[i]=0.f; g_sq3[i]=0.f; }
    if (i < H2){ g_sum2[i]=0.f; g_sq2[i]=0.f; }
    if (i < H3){ g_sum1[i]=0.f; g_sq1[i]=0.f; }
    if (i < 3){ g_sumd[i]=0.f; g_sqd[i]=0.f; }
}

// covariance features + Linear(12,64) + BN stats
__global__ __launch_bounds__(256) void k_cov_e1(
    const float* __restrict__ data, const int* __restrict__ knn,
    const float* __restrict__ w, const float* __restrict__ bias)
{
    __shared__ float Ws[12*H3];
    __shared__ float bs[H3];
    __shared__ float x0s[256*12];
    __shared__ float ssum[H3], ssq[H3];
    int t = threadIdx.x;
    for (int i = t; i < 12*H3; i += 256) Ws[i] = w[i];
    if (t < H3){ bs[t] = bias[t]; ssum[t]=0.f; ssq[t]=0.f; }

    int gi = blockIdx.x*256 + t;
    int b = gi >> 13;
    const int* kp = knn + (size_t)gi*KNB;
    float sx=0,sy=0,sz=0,sxx=0,sxy=0,sxz=0,syy=0,syz=0,szz=0;
    #pragma unroll
    for (int k=0;k<KNB;k++){
        int j = kp[k];
        const float* p = data + ((size_t)(b*NN + j))*3;
        float x=p[0], y=p[1], z=p[2];
        sx+=x; sy+=y; sz+=z;
        sxx+=x*x; sxy+=x*y; sxz+=x*z; syy+=y*y; syz+=y*z; szz+=z*z;
    }
    float mx=sx*(1.f/16.f), my=sy*(1.f/16.f), mz=sz*(1.f/16.f);
    const float i15 = 1.f/15.f;
    float cxx=(sxx-16.f*mx*mx)*i15, cxy=(sxy-16.f*mx*my)*i15, cxz=(sxz-16.f*mx*mz)*i15;
    float cyy=(syy-16.f*my*my)*i15, cyz=(syz-16.f*my*mz)*i15, czz=(szz-16.f*mz*mz)*i15;
    float* xr = &x0s[t*12];
    xr[0]=data[(size_t)gi*3+0]; xr[1]=data[(size_t)gi*3+1]; xr[2]=data[(size_t)gi*3+2];
    xr[3]=cxx; xr[4]=cxy; xr[5]=cxz; xr[6]=cxy; xr[7]=cyy; xr[8]=cyz; xr[9]=cxz; xr[10]=cyz; xr[11]=czz;
    __syncthreads();

    int c = t & 63;
    float bsum=0.f, bsq=0.f;
    float* outp = g_pre1 + (size_t)blockIdx.x*256*H3;
    #pragma unroll 4
    for (int kq=0;kq<64;kq++){
        int e = t + kq*256;
        const float* x0 = &x0s[(e>>6)*12];
        float v = bs[c];
        #pragma unroll
        for (int j=0;j<12;j++) v = fmaf(x0[j], Ws[j*H3+c], v);
        outp[e] = v;
        bsum += v; bsq += v*v;
    }
    atomicAdd(&ssum[c], bsum); atomicAdd(&ssq[c], bsq);
    __syncthreads();
    if (t < H3){ atomicAdd(&g_sum1[t], ssum[t]); atomicAdd(&g_sq1[t], ssq[t]); }
}

template<int C, int LAYER>
__global__ void k_fin(const float* __restrict__ g, const float* __restrict__ be){
    int c = threadIdx.x;
    const float* su = (LAYER==1)? g_sum1 : g_sum2;
    const float* sq = (LAYER==1)? g_sq1  : g_sq2;
    float* bn = (LAYER==1)? g_bn1 : g_bn2;
    float invM = 1.f/(float)MTOT;
    float m = su[c]*invM;
    float v = fmaxf(sq[c]*invM - m*m, 0.f);
    float sc = g[c]*rsqrtf(v+EPSBN);
    bn[c]=sc; bn[C+c]= fmaf(-m, sc, be[c]);
}

// BN+ReLU applied on the fly, aggregate self + 16 neighbors, /17
template<int C, int LAYER>
__global__ __launch_bounds__(256) void k_agg(const int* __restrict__ knn){
    const int NPB = 256/C;
    __shared__ int sidx[NPB][KNB];
    int t = threadIdx.x;
    int n0 = blockIdx.x*NPB;
    if (t < NPB*KNB) sidx[t>>4][t&15] = knn[(size_t)(n0 + (t>>4))*KNB + (t&15)];
    __syncthreads();
    int nl = t / C; int c = t % C;
    int gi = n0 + nl;
    int base = (gi >> 13) * NN;
    const float* pre = (LAYER==1)? g_pre1 : g_pre2;
    const float* bn  = (LAYER==1)? g_bn1  : g_bn2;
    float* agg = (LAYER==1)? g_agg1 : g_agg2;
    float sc = bn[c], sh = bn[C+c];
    float a = fmaxf(fmaf(pre[(size_t)gi*C + c], sc, sh), 0.f);
    #pragma unroll
    for (int k=0;k<KNB;k++){
        int nb = base + sidx[nl][k];
        a += fmaxf(fmaf(pre[(size_t)nb*C + c], sc, sh), 0.f);
    }
    agg[(size_t)gi*C + c] = a * (1.f/17.f);
}

// tiled GEMM (64 nodes x 128 ch per block), f32x2 FMA, fused BN stats (+minmax, no output write for layer 2)
template<int CIN, int COUT, bool WOUT, bool MM, int LAYER>
__global__ __launch_bounds__(256) void k_gemm(const float* __restrict__ W, const float* __restrict__ bias){
    const int ASTR = 72;
    __shared__ __align__(16) float As[32*ASTR];
    __shared__ __align__(16) float Ws[32*128];
    __shared__ float ssum[128], ssq[128];
    __shared__ uint smx[128], smn[128];
    const float* in = (LAYER==1)? g_agg1 : g_agg2;
    float* sumg = (LAYER==1)? g_sum2 : g_sum3;
    float* sqg  = (LAYER==1)? g_sq2  : g_sq3;
    int t = threadIdx.x;
    int n0 = blockIdx.x*64;
    int cb = blockIdx.y*128;
    int cq = (t & 31)*4;
    int nb = (t >> 5)*8;
    if (t < 128){ ssum[t]=0.f; ssq[t]=0.f; if (MM){ smx[t]=0u; smn[t]=0xFFFFFFFFu; } }
    ull acc[8][2];
    #pragma unroll
    for (int n=0;n<8;n++){ acc[n][0]=0ull; acc[n][1]=0ull; }

    for (int kk=0; kk<CIN; kk+=32){
        {
            int f = t & 31; int nA = t >> 5;
            #pragma unroll
            for (int i=0;i<8;i++)
                As[f*ASTR + nA + 8*i] = in[(size_t)(n0 + nA + 8*i)*CIN + kk + f];
        }
        #pragma unroll
        for (int i=0;i<16;i++){
            int idx = t + 256*i;
            int f = idx >> 7; int c = idx & 127;
            Ws[f*128 + c] = W[(size_t)(kk+f)*COUT + cb + c];
        }
        __syncthreads();
        #pragma unroll
        for (int f=0; f<32; f++){
            float4 w = *(const float4*)&Ws[f*128 + cq];
            ull w01 = pack2(w.x, w.y), w23 = pack2(w.z, w.w);
            float4 a0 = *(const float4*)&As[f*ASTR + nb];
            float4 a1 = *(const float4*)&As[f*ASTR + nb + 4];
            float av[8] = {a0.x,a0.y,a0.z,a0.w,a1.x,a1.y,a1.z,a1.w};
            #pragma unroll
            for (int n=0;n<8;n++){
                ull a2 = pack2(av[n], av[n]);
                ffma2(acc[n][0], a2, w01);
                ffma2(acc[n][1], a2, w23);
            }
        }
        __syncthreads();
    }

    float bv[4], s[4], q[4], mx[4], mn[4];
    #pragma unroll
    for (int j=0;j<4;j++){ bv[j]=bias[cb+cq+j]; s[j]=0.f; q[j]=0.f; mx[j]=-3.402823466e38f; mn[j]=3.402823466e38f; }
    #pragma unroll
    for (int n=0;n<8;n++){
        float2 p0=unpack2(acc[n][0]), p1=unpack2(acc[n][1]);
        float v[4] = {p0.x+bv[0], p0.y+bv[1], p1.x+bv[2], p1.y+bv[3]};
        #pragma unroll
        for (int j=0;j<4;j++){
            s[j]+=v[j]; q[j]+=v[j]*v[j];
            if (MM){ mx[j]=fmaxf(mx[j],v[j]); mn[j]=fminf(mn[j],v[j]); }
        }
        if (WOUT){
            float4 o = make_float4(v[0],v[1],v[2],v[3]);
            *(float4*)(&g_pre2[(size_t)(n0+nb+n)*COUT + cb + cq]) = o;
        }
    }
    #pragma unroll
    for (int j=0;j<4;j++){
        atomicAdd(&ssum[cq+j], s[j]); atomicAdd(&ssq[cq+j], q[j]);
        if (MM){ atomicMax(&smx[cq+j], fkey(mx[j])); atomicMin(&smn[cq+j], fkey(mn[j])); }
    }
    __syncthreads();
    if (t < 128){
        atomicAdd(&sumg[cb+t], ssum[t]);
        atomicAdd(&sqg [cb+t], ssq[t]);
        if (MM){
            int b = n0 >> 13;
            atomicMax(&g_maxk[b*H1 + cb + t], smx[t]);
            atomicMin(&g_mink[b*H1 + cb + t], smn[t]);
        }
    }
}

// finalize BN3 + pooled = relu(max over nodes of BN'd value)
__global__ void k_fin3pool(const float* __restrict__ g, const float* __restrict__ be){
    int c = threadIdx.x;
    int b = blockIdx.x;
    float invM = 1.f/(float)MTOT;
    float m = g_sum3[c]*invM;
    float v = fmaxf(g_sq3[c]*invM - m*m, 0.f);
    float sc = g[c]*rsqrtf(v+EPSBN);
    float sh = fmaf(-m, sc, be[c]);
    float mx = keyf(g_maxk[b*H1+c]);
    float mn = keyf(g_mink[b*H1+c]);
    float val = (sc >= 0.f) ? fmaf(mx, sc, sh) : fmaf(mn, sc, sh);
    g_pool[b*H1+c] = fmaxf(val, 0.f);
}

// e2 linear: pre4[b] = pool[b] @ W + bias   (block per batch)
__global__ __launch_bounds__(512) void k_e2(const float* __restrict__ W, const float* __restrict__ bias){
    __shared__ float sp[H1];
    int b = blockIdx.x, c = threadIdx.x;
    sp[c] = g_pool[b*H1 + c];
    __syncthreads();
    float acc = bias[c];
    #pragma unroll 4
    for (int f=0; f<H1; f++) acc = fmaf(sp[f], W[(size_t)f*H1 + c], acc);
    g_pre4[b*H1 + c] = acc;
}

// e2 BN(M=16)+ReLU -> code; decoder per-batch dots; analytic d1 BN params
__global__ __launch_bounds__(512) void k_code2(
    const float* __restrict__ eg, const float* __restrict__ ebe,
    const float* __restrict__ d1w, const float* __restrict__ d1b,
    const float* __restrict__ d1g, const float* __restrict__ d1be,
    const float* __restrict__ d2w, const float* __restrict__ d2b)
{
    __shared__ float scm[BB*H1];
    int t = threadIdx.x;
    float vals[16]; float s = 0.f;
    #pragma unroll
    for (int b=0;b<16;b++){ vals[b]=g_pre4[b*H1+t]; s+=vals[b]; }
    float m = s*(1.f/16.f);
    float q = 0.f;
    #pragma unroll
    for (int b=0;b<16;b++){ float d=vals[b]-m; q+=d*d; }
    float scl = eg[t]*rsqrtf(q*(1.f/16.f)+EPSBN);
    float sh = ebe[t];
    #pragma unroll
    for (int b=0;b<16;b++) scm[b*H1+t] = fmaxf(fmaf(vals[b]-m, scl, sh), 0.f);
    __syncthreads();

    int w = t>>5, lane = t&31;
    if (w < 6){
        for (int d = w*16; d < w*16+16; d++){
            int layer = d/48; int r = d%48; int b = r/3; int c = r%3;
            const float* Wd = layer ? d2w : d1w;
            float p = 0.f;
            for (int f=lane; f<H1; f+=32) p = fmaf(scm[b*H1+f], Wd[f*3+c], p);
            #pragma unroll
            for (int o=16;o;o>>=1) p += __shfl_xor_sync(0xffffffffu, p, o);
            if (lane==0){
                if (layer) g_dc2[b*3+c] = p + d2b[c];
                else       g_dc1[b*3+c] = p + d1b[c];
            }
        }
    }
    __syncthreads();
    if (w < 3){
        float wx = d1w[1536 + w], wy = d1w[1539 + w];
        float sG = 0.f;
        for (int n=lane; n<NN; n+=32){
            int ix = n/65, iy = n - ix*65;
            float gx = 1.f + ix*(119.f/128.f);
            float gy = 1.f + iy*(59.f/64.f);
            sG += gx*wx + gy*wy;
        }
        #pragma unroll
        for (int o=16;o;o>>=1) sG += __shfl_xor_sync(0xffffffffu, sG, o);
        float mG = sG*(1.f/8192.f);
        float qG = 0.f;
        for (int n=lane; n<NN; n+=32){
            int ix = n/65, iy = n - ix*65;
            float gx = 1.f + ix*(119.f/128.f);
            float gy = 1.f + iy*(59.f/64.f);
            float d = gx*wx + gy*wy - mG;
            qG += d*d;
        }
        #pragma unroll
        for (int o=16;o;o>>=1) qG += __shfl_xor_sync(0xffffffffu, qG, o);
        if (lane==0){
            float vG = qG*(1.f/8192.f);
            float sA=0.f;
            #pragma unroll
            for (int b=0;b<16;b++) sA += g_dc1[b*3+w];
            float mA = sA*(1.f/16.f);
            float qA=0.f;
            #pragma unroll
            for (int b=0;b<16;b++){ float d=g_dc1[b*3+w]-mA; qA+=d*d; }
            float vA = qA*(1.f/16.f);
            float mean = mA + mG;
            float var = fmaxf(vA + vG, 0.f);
            float sc1 = d1g[w]*rsqrtf(var+EPSBN);
            g_d1p[w]=sc1; g_d1p[3+w]= d1be[w] - mean*sc1;
        }
    }
}

// per-node decode: z1 (d1+BN+ReLU), z2pre (d2), write z2pre + d2 BN stats
__global__ __launch_bounds__(256) void k_decode(const float* __restrict__ d1w, const float* __restrict__ d2w){
    __shared__ float ss[3], sq_[3];
    int t = threadIdx.x;
    if (t<3){ ss[t]=0.f; sq_[t]=0.f; }
    __syncthreads();
    int gi = blockIdx.x*256 + t;
    int n = gi & (NN-1);
    int b = gi >> 13;
    int ix = n/65, iy = n - ix*65;
    float gx = 1.f + ix*(119.f/128.f);
    float gy = 1.f + iy*(59.f/64.f);
    float z1[3];
    #pragma unroll
    for (int c=0;c<3;c++){
        float pre = g_dc1[b*3+c] + gx*d1w[1536+c] + gy*d1w[1539+c];
        z1[c] = fmaxf(fmaf(pre, g_d1p[c], g_d1p[3+c]), 0.f);
    }
    float v[3];
    #pragma unroll
    for (int c=0;c<3;c++){
        v[c] = g_dc2[b*3+c] + z1[0]*d2w[1536+c] + z1[1]*d2w[1539+c] + z1[2]*d2w[1542+c];
        g_z2[(size_t)gi*3+c] = v[c];
    }
    int lane = t & 31;
    #pragma unroll
    for (int c=0;c<3;c++){
        float sv = v[c], qv = v[c]*v[c];
        #pragma unroll
        for (int o=16;o;o>>=1){ sv += __shfl_xor_sync(0xffffffffu, sv, o); qv += __shfl_xor_sync(0xffffffffu, qv, o); }
        if (lane==0){ atomicAdd(&ss[c], sv); atomicAdd(&sq_[c], qv); }
    }
    __syncthreads();
    if (t<3){ atomicAdd(&g_sumd[t], ss[t]); atomicAdd(&g_sqd[t], sq_[t]); }
}

__global__ void k_out(float* __restrict__ out, const float* __restrict__ g, const float* __restrict__ be){
    int i = blockIdx.x*blockDim.x + threadIdx.x;
    if (i >= MTOT*3) return;
    int c = i % 3;
    float invM = 1.f/(float)MTOT;
    float m = g_sumd[c]*invM;
    float v = fmaxf(g_sqd[c]*invM - m*m, 0.f);
    float sc = g[c]*rsqrtf(v+EPSBN);
    out[i] = fmaxf(fmaf(g_z2[i]-m, sc, be[c]), 0.f);
}

// ---------------- launch ----------------
extern "C" void kernel_launch(void* const* d_in, const int* in_sizes, int n_in,
                              void* d_out, int out_size)
{
    const float* data = (const float*)d_in[0];
    const int*   knn  = (const int*)  d_in[1];
    const float* e1w  = (const float*)d_in[2];
    const float* e1b  = (const float*)d_in[3];
    const float* e1g  = (const float*)d_in[4];
    const float* e1be = (const float*)d_in[5];
    const float* gc1w = (const float*)d_in[6];
    const float* gc1b = (const float*)d_in[7];
    const float* g1g  = (const float*)d_in[8];
    const float* g1be = (const float*)d_in[9];
    const float* gc2w = (const float*)d_in[10];
    const float* gc2b = (const float*)d_in[11];
    const float* g2g  = (const float*)d_in[12];
    const float* g2be = (const float*)d_in[13];
    const float* e2w  = (const float*)d_in[14];
    const float* e2b  = (const float*)d_in[15];
    const float* e2g  = (const float*)d_in[16];
    const float* e2be = (const float*)d_in[17];
    const float* d1w  = (const float*)d_in[18];
    const float* d1b  = (const float*)d_in[19];
    const float* d1g  = (const float*)d_in[20];
    const float* d1be = (const float*)d_in[21];
    const float* d2w  = (const float*)d_in[22];
    const float* d2b  = (const float*)d_in[23];
    const float* d2g  = (const float*)d_in[24];
    const float* d2be = (const float*)d_in[25];
    float* out = (float*)d_out;

    k_zero<<<8, 1024>>>();
    k_cov_e1<<<MTOT/256, 256>>>(data, knn, e1w, e1b);
    k_fin<H3,1><<<1, H3>>>(e1g, e1be);
    k_agg<H3,1><<<MTOT/4, 256>>>(knn);
    k_gemm<H3,H2,true,false,1><<<dim3(MTOT/64,1), 256>>>(gc1w, gc1b);
    k_fin<H2,2><<<1, H2>>>(g1g, g1be);
    k_agg<H2,2><<<MTOT/2, 256>>>(knn);
    k_gemm<H2,H1,false,true,2><<<dim3(MTOT/64,4), 256>>>(gc2w, gc2b);
    k_fin3pool<<<BB, H1>>>(g2g, g2be);
    k_e2<<<BB, H1>>>(e2w, e2b);
    k_code2<<<1, 512>>>(e2g, e2be, d1w, d1b, d1g, d1be, d2w, d2b);
    k_decode<<<MTOT/256, 256>>>(d1w, d2w);
    k_out<<<(MTOT*3+255)/256, 256>>>(out, d2g, d2be);
}